// round 1
// baseline (speedup 1.0000x reference)
#include <cuda_runtime.h>
#include <math.h>

// Problem constants
#define NTAU 64
#define NANG 64
#define KH_ 5
#define KW_ 5
#define OC_ 32
#define IC_ 8
#define NB 4
#define XY 256
#define NSAMP (NB * XY)          // 1024
#define HOUT 60                  // NTAU - KH + 1
#define WOUT 64                  // NANG (circular)
#define WPEROC 200               // IC*KH*KW
#define WTOT (OC_ * WPEROC)      // 6400

// Conv kernel config
#define ROWS 72                  // padded smem row stride (68 used, 72 for 16B align)
#define TILE_FLOATS (IC_ * NTAU * ROWS)   // 36864
#define CONV_THREADS 512
#define NWARPS (CONV_THREADS / 32)        // 16
#define SMEM_BYTES ((TILE_FLOATS + WTOT + OC_ * NWARPS) * 4 + OC_ * NWARPS * 4)  // 177152

// Scratch (static device memory; no allocation APIs used)
__device__ float g_xt[(size_t)NSAMP * IC_ * NTAU * NANG];  // 134 MB transposed input
__device__ float g_w[WTOT];
__device__ float g_val[NSAMP * OC_];
__device__ int   g_idx[NSAMP * OC_];

// ---------------------------------------------------------------------------
// Weight normalization: w = g * v / ||v||_2 (per output channel)
// ---------------------------------------------------------------------------
__global__ void prep_weights(const float* __restrict__ v, const float* __restrict__ g) {
    __shared__ float scale[OC_];
    int tid = threadIdx.x;
    if (tid < OC_) {
        const float* p = v + tid * WPEROC;
        float s = 0.f;
        for (int k = 0; k < WPEROC; ++k) s += p[k] * p[k];
        scale[tid] = g[tid] / sqrtf(s);
    }
    __syncthreads();
    for (int i = tid; i < WTOT; i += blockDim.x)
        g_w[i] = v[i] * scale[i / WPEROC];
}

// ---------------------------------------------------------------------------
// Transpose (B,C,ta,xy) -> (n=b*256+xy, c, ta). Tiled 32x32 via smem.
// ---------------------------------------------------------------------------
__global__ void transpose_kernel(const float* __restrict__ x) {
    __shared__ float t[32][33];
    int bc  = blockIdx.z;            // b*8 + c
    int ta0 = blockIdx.x << 5;
    int xy0 = blockIdx.y << 5;
    int tx = threadIdx.x, ty = threadIdx.y;  // 32 x 8
    const float* src = x + (size_t)bc * 4096 * 256;
#pragma unroll
    for (int k = 0; k < 4; ++k)
        t[ty + k * 8][tx] = src[(size_t)(ta0 + ty + k * 8) * 256 + xy0 + tx];
    __syncthreads();
    int b = bc >> 3, c = bc & 7;
#pragma unroll
    for (int k = 0; k < 4; ++k) {
        int xy = xy0 + ty + k * 8;
        int ta = ta0 + tx;
        g_xt[((size_t)(b * XY + xy) * IC_ + c) * 4096 + ta] = t[tx][ty + k * 8];
    }
}

// ---------------------------------------------------------------------------
// Per-sample conv (circular in theta) + global max/argmax per oc.
// One block per sample n. Full padded tile + weights in SMEM.
// Register blocking: 2 quads (4 consecutive w) x 2 oc per thread.
// ---------------------------------------------------------------------------
extern __shared__ float smem[];

__global__ void __launch_bounds__(CONV_THREADS, 1) conv_argmax_kernel() {
    float* tile = smem;                          // IC_*64*72
    float* ws   = smem + TILE_FLOATS;            // 6400
    float* pv   = ws + WTOT;                     // OC_*NWARPS
    int*   pi   = (int*)(pv + OC_ * NWARPS);     // OC_*NWARPS

    int tid = threadIdx.x;
    int n = blockIdx.x;
    const float4* s4 = (const float4*)(g_xt + (size_t)n * (IC_ * NTAU * NANG));

    // Load tile (vectorized, coalesced gmem, conflict-free STS.128)
    for (int i = tid; i < IC_ * NTAU * (NANG / 4); i += CONV_THREADS) {
        int c = i >> 10, t = (i >> 4) & 63, a4 = i & 15;
        float4 vv = s4[i];
        *(float4*)&tile[c * (NTAU * ROWS) + t * ROWS + (a4 << 2)] = vv;
    }
    // Circular wrap: columns 64..67 = columns 0..3
    for (int i = tid; i < IC_ * NTAU; i += CONV_THREADS) {
        int c = i >> 6, t = i & 63;
        float4 vv = s4[i << 4];
        *(float4*)&tile[c * (NTAU * ROWS) + t * ROWS + 64] = vv;
    }
    for (int i = tid; i < WTOT; i += CONV_THREADS) ws[i] = g_w[i];
    __syncthreads();

    // Quad assignment: 960 quads of 4 outputs; flat pos = 4*qid + xq (ascending)
    int q0 = tid;                    // always < 960
    int q1 = tid + CONV_THREADS;
    bool v1 = (q1 < 960);
    if (!v1) q1 = 0;
    int h0 = q0 >> 4, w0 = (q0 & 15) << 2;
    int h1 = q1 >> 4, w1 = (q1 & 15) << 2;

    int lane = tid & 31, warp = tid >> 5;
    const float* base0 = tile + h0 * ROWS + w0;
    const float* base1 = tile + h1 * ROWS + w1;

#pragma unroll 1
    for (int op = 0; op < OC_ / 2; ++op) {
        int oc0 = op * 2;
        const float* wp0 = ws + oc0 * WPEROC;
        const float* wp1 = wp0 + WPEROC;

        float acc00[4], acc01[4], acc10[4], acc11[4];  // [oc][quad]
#pragma unroll
        for (int xq = 0; xq < 4; ++xq) { acc00[xq] = 0.f; acc01[xq] = 0.f; acc10[xq] = 0.f; acc11[xq] = 0.f; }

#pragma unroll 1
        for (int ic = 0; ic < IC_; ++ic) {
            const float* r0 = base0 + ic * (NTAU * ROWS);
            const float* r1 = base1 + ic * (NTAU * ROWS);
            const float* wi0 = wp0 + ic * 25;
            const float* wi1 = wp1 + ic * 25;
#pragma unroll
            for (int kh = 0; kh < KH_; ++kh) {
                float wa[KW_], wb[KW_];
#pragma unroll
                for (int kw = 0; kw < KW_; ++kw) {
                    wa[kw] = wi0[kh * 5 + kw];
                    wb[kw] = wi1[kh * 5 + kw];
                }
                const float* p0 = r0 + kh * ROWS;
                const float* p1 = r1 + kh * ROWS;
                float4 a0 = *(const float4*)p0;
                float4 a1 = *(const float4*)(p0 + 4);
                float4 b0 = *(const float4*)p1;
                float4 b1 = *(const float4*)(p1 + 4);
                float in0[8] = {a0.x, a0.y, a0.z, a0.w, a1.x, a1.y, a1.z, a1.w};
                float in1[8] = {b0.x, b0.y, b0.z, b0.w, b1.x, b1.y, b1.z, b1.w};
#pragma unroll
                for (int kw = 0; kw < KW_; ++kw) {
#pragma unroll
                    for (int xq = 0; xq < 4; ++xq) {
                        acc00[xq] = fmaf(in0[xq + kw], wa[kw], acc00[xq]);
                        acc10[xq] = fmaf(in0[xq + kw], wb[kw], acc10[xq]);
                        acc01[xq] = fmaf(in1[xq + kw], wa[kw], acc01[xq]);
                        acc11[xq] = fmaf(in1[xq + kw], wb[kw], acc11[xq]);
                    }
                }
            }
        }

        // max/argmax for the two ocs (first-occurrence semantics)
#pragma unroll
        for (int o = 0; o < 2; ++o) {
            const float* aq0 = (o == 0) ? acc00 : acc10;
            const float* aq1 = (o == 0) ? acc01 : acc11;
            float bv = -1e30f;
            int bi = 0x7FFFFFFF;
#pragma unroll
            for (int xq = 0; xq < 4; ++xq) {
                float val = aq0[xq];
                int pos = h0 * 64 + w0 + xq;
                if (val > bv) { bv = val; bi = pos; }
            }
            if (v1) {
#pragma unroll
                for (int xq = 0; xq < 4; ++xq) {
                    float val = aq1[xq];
                    int pos = h1 * 64 + w1 + xq;
                    if (val > bv) { bv = val; bi = pos; }
                }
            }
#pragma unroll
            for (int off = 16; off; off >>= 1) {
                float ov = __shfl_down_sync(0xffffffffu, bv, off);
                int   oi = __shfl_down_sync(0xffffffffu, bi, off);
                if (ov > bv || (ov == bv && oi < bi)) { bv = ov; bi = oi; }
            }
            if (lane == 0) {
                pv[(oc0 + o) * NWARPS + warp] = bv;
                pi[(oc0 + o) * NWARPS + warp] = bi;
            }
        }
    }
    __syncthreads();
    if (tid < OC_) {
        float bv = pv[tid * NWARPS];
        int   bi = pi[tid * NWARPS];
#pragma unroll
        for (int r = 1; r < NWARPS; ++r) {
            float ov = pv[tid * NWARPS + r];
            int   oi = pi[tid * NWARPS + r];
            if (ov > bv || (ov == bv && oi < bi)) { bv = ov; bi = oi; }
        }
        g_val[n * OC_ + tid] = bv;
        g_idx[n * OC_ + tid] = bi;
    }
}

// ---------------------------------------------------------------------------
// Softmax over spatial (256) per (b,oc) + tau/phase encoding.
// One block per (b, oc), thread = xy.
// ---------------------------------------------------------------------------
__global__ void finalize_kernel(float* __restrict__ out) {
    int b = blockIdx.x, oc = blockIdx.y;
    int xy = threadIdx.x;
    int n = b * XY + xy;
    float v = g_val[n * OC_ + oc];
    int idx = g_idx[n * OC_ + oc];

    __shared__ float sm[8];
    __shared__ float s4[8][4];
    __shared__ float bc[5];
    int lane = xy & 31, warp = xy >> 5;

    // block max (for stable softmax)
    float m = v;
#pragma unroll
    for (int off = 16; off; off >>= 1) m = fmaxf(m, __shfl_xor_sync(0xffffffffu, m, off));
    if (lane == 0) sm[warp] = m;
    __syncthreads();
    if (xy == 0) {
        float mm = sm[0];
#pragma unroll
        for (int r = 1; r < 8; ++r) mm = fmaxf(mm, sm[r]);
        bc[0] = mm;
    }
    __syncthreads();
    m = bc[0];

    float e = expf(v - m);
    float tau = (float)idx * (1.0f / 4096.0f);
    float phase = (float)(idx & 63) * 0.09817477042468103f;  // 2*pi/64
    float cp = cosf(phase), sp = sinf(phase);

    float se = e, st = e * tau, sc = e * cp, ss = e * sp;
#pragma unroll
    for (int off = 16; off; off >>= 1) {
        se += __shfl_xor_sync(0xffffffffu, se, off);
        st += __shfl_xor_sync(0xffffffffu, st, off);
        sc += __shfl_xor_sync(0xffffffffu, sc, off);
        ss += __shfl_xor_sync(0xffffffffu, ss, off);
    }
    if (lane == 0) { s4[warp][0] = se; s4[warp][1] = st; s4[warp][2] = sc; s4[warp][3] = ss; }
    __syncthreads();
    if (xy == 0) {
        float a = 0, b2 = 0, c = 0, d = 0;
#pragma unroll
        for (int r = 0; r < 8; ++r) { a += s4[r][0]; b2 += s4[r][1]; c += s4[r][2]; d += s4[r][3]; }
        bc[1] = a; bc[2] = b2; bc[3] = c; bc[4] = d;
    }
    __syncthreads();
    float Se = bc[1], St = bc[2], Sc = bc[3], Ss = bc[4];

    float rel = phase - atan2f(Ss, Sc);
    size_t base = (size_t)n * (4 * OC_) + oc;
    out[base]          = v;
    out[base + OC_]    = tau - St / Se;
    out[base + 2*OC_]  = cosf(rel);
    out[base + 3*OC_]  = sinf(rel);
}

// ---------------------------------------------------------------------------
extern "C" void kernel_launch(void* const* d_in, const int* in_sizes, int n_in,
                              void* d_out, int out_size) {
    const float* x = (const float*)d_in[0];       // (4,8,64,64,16,16)
    const float* v = (const float*)d_in[1];       // (32,8,5,5)
    const float* g = (const float*)d_in[2];       // (32,)
    float* out = (float*)d_out;                   // (4,16,16,128,1,1)

    cudaFuncSetAttribute(conv_argmax_kernel,
                         cudaFuncAttributeMaxDynamicSharedMemorySize, SMEM_BYTES);

    prep_weights<<<1, 256>>>(v, g);
    transpose_kernel<<<dim3(128, 8, 32), dim3(32, 8)>>>(x);
    conv_argmax_kernel<<<NSAMP, CONV_THREADS, SMEM_BYTES>>>();
    finalize_kernel<<<dim3(NB, OC_), 256>>>(out);
}